// round 9
// baseline (speedup 1.0000x reference)
#include <cuda_runtime.h>
#include <cstdint>

#define N_ATOMS 4096
#define L_WORDS 65536
#define DD 10
#define KS 23
#define KSPLIT 2
#define KCHUNK (N_ATOMS / KSPLIT)   // 2048
#define NT 256
#define SMEM_BYTES 81920
#define MVROWS 8
#define MVTILE 64

typedef unsigned long long ull;

// ---------------- scratch ----------------
__device__ float g_xs[N_ATOMS * DD];
__device__ ull   g_hs[8 * 5 * (N_ATOMS / 8)];
__device__ uint4 g_Ab[(size_t)N_ATOMS * N_ATOMS / 8];
__device__ float g_pp[KSPLIT][N_ATOMS * DD];
__device__ float g_cnn[2][L_WORDS * DD];
__device__ float g_comp[DD];
__device__ float g_cpart[512 * DD];
__device__ float g_part[512 * DD];
__device__ unsigned g_bar;    // full-grid
__device__ unsigned g_barG;   // GNN chain
__device__ unsigned g_barC;   // CNN chain

// ---------------- helpers ----------------
__device__ __forceinline__ ull pack2(float x, float y) {
    ull r; asm("mov.b64 %0, {%1, %2};" : "=l"(r) : "f"(x), "f"(y)); return r;
}
__device__ __forceinline__ void unpack2(ull v, float& x, float& y) {
    asm("mov.b64 {%0, %1}, %2;" : "=f"(x), "=f"(y) : "l"(v));
}
__device__ __forceinline__ void fma2(ull& d, ull a, ull b) {
    asm("fma.rn.f32x2 %0, %1, %2, %0;" : "+l"(d) : "l"(a), "l"(b));
}
__device__ __forceinline__ unsigned bfpack(float lo, float hi) {
    unsigned r;
    asm("cvt.rn.bf16x2.f32 %0, %1, %2;" : "=r"(r) : "f"(hi), "f"(lo));
    return r;
}

// ---------------- barriers (monotonic; replay-safe) ----------------
__device__ __forceinline__ void pbar(unsigned* ctr, unsigned count) {
    __syncthreads();
    if (threadIdx.x == 0) {
        __threadfence();
        unsigned old = atomicAdd(ctr, 1u);
        unsigned target = (old / count + 1u) * count;
        while (*(volatile unsigned*)ctr < target) { }
    }
    __syncthreads();
    __threadfence();
}

// ---------------- hs for one atom ----------------
__device__ __forceinline__ void hs_store(int m, const float* x,
                                         const float* Wgl, const float* bgl) {
    int k8 = m & 7, base = m >> 3;
#pragma unroll
    for (int p = 0; p < 5; p++) {
        float h0 = bgl[2 * p], h1 = bgl[2 * p + 1];
#pragma unroll
        for (int c = 0; c < DD; c++) {
            h0 = fmaf(x[c], Wgl[(2 * p) * DD + c], h0);
            h1 = fmaf(x[c], Wgl[(2 * p + 1) * DD + c], h1);
        }
        g_hs[(k8 * 5 + p) * (N_ATOMS / 8) + base] =
            pack2(fmaxf(h0, 0.f), fmaxf(h1, 0.f));
    }
}

__device__ __forceinline__ void fill_hs(ull* sh, int kb) {
    for (int i = threadIdx.x; i < 40 * (KCHUNK / 8); i += NT) {
        int kp = i / (KCHUNK / 8), j = i % (KCHUNK / 8);
        sh[i] = g_hs[kp * (N_ATOMS / 8) + kb * (KCHUNK / 8) + j];
    }
    __syncthreads();
}

// ---------------- layer-0 mv tile: fp32 A read + bf16 write, 32 rows ----------
__device__ __forceinline__ void mv0_tile(char* smem_raw, int u, const float* A) {
    ull* sh = (ull*)smem_raw;
    const int tid = threadIdx.x;
    const int rowblk = u & 127, kb = u >> 7;
    fill_hs(sh, kb);

    const int warp = tid >> 5, lane = tid & 31;
    const int row0 = rowblk * 32 + warp * 4;
    float* pout = g_pp[kb];

    const float4* Af[4];
    uint4* Ao[4];
#pragma unroll
    for (int r = 0; r < 4; r++) {
        Af[r] = (const float4*)A + (size_t)(row0 + r) * (N_ATOMS / 4) + kb * (KCHUNK / 4);
        Ao[r] = g_Ab + (size_t)(row0 + r) * (N_ATOMS / 8) + kb * (KCHUNK / 8);
    }

    ull acc[4][5];
#pragma unroll
    for (int r = 0; r < 4; r++)
#pragma unroll
        for (int p = 0; p < 5; p++) acc[r][p] = 0ull;

    for (int it = 0; it < KCHUNK / 256; it++) {
        int q = it * 32 + lane;
        float4 lo[4], hi[4];
#pragma unroll
        for (int r = 0; r < 4; r++) {
            lo[r] = Af[r][2 * q];
            hi[r] = Af[r][2 * q + 1];
            uint4 o;
            o.x = bfpack(lo[r].x, lo[r].y);
            o.y = bfpack(lo[r].z, lo[r].w);
            o.z = bfpack(hi[r].x, hi[r].y);
            o.w = bfpack(hi[r].z, hi[r].w);
            Ao[r][q] = o;
        }
#pragma unroll
        for (int k8 = 0; k8 < 8; k8++) {
            ull h[5];
#pragma unroll
            for (int p = 0; p < 5; p++)
                h[p] = sh[(k8 * 5 + p) * (KCHUNK / 8) + q];
#pragma unroll
            for (int r = 0; r < 4; r++) {
                float av = (k8 == 0) ? lo[r].x : (k8 == 1) ? lo[r].y
                         : (k8 == 2) ? lo[r].z : (k8 == 3) ? lo[r].w
                         : (k8 == 4) ? hi[r].x : (k8 == 5) ? hi[r].y
                         : (k8 == 6) ? hi[r].z : hi[r].w;
                ull v = pack2(av, av);
#pragma unroll
                for (int p = 0; p < 5; p++) fma2(acc[r][p], v, h[p]);
            }
        }
    }

#pragma unroll
    for (int r = 0; r < 4; r++) {
        float f[DD];
#pragma unroll
        for (int p = 0; p < 5; p++) unpack2(acc[r][p], f[2 * p], f[2 * p + 1]);
#pragma unroll
        for (int d = 0; d < DD; d++)
#pragma unroll
            for (int o = 16; o > 0; o >>= 1)
                f[d] += __shfl_down_sync(0xffffffffu, f[d], o);
        if (lane == 0)
#pragma unroll
            for (int d = 0; d < DD; d++) pout[(row0 + r) * DD + d] = f[d];
    }
}

// ---------------- bf16 mv tile (layers 1,2): 64 rows ----------------
__device__ __forceinline__ void mv_tile(char* smem_raw, int u) {
    ull* sh = (ull*)smem_raw;
    const int tid = threadIdx.x;
    const int rowblk = u & 63, kb = u >> 6;
    fill_hs(sh, kb);

    const int warp = tid >> 5, lane = tid & 31;
    const int row0 = rowblk * MVTILE + warp * MVROWS;
    float* pout = g_pp[kb];
    const int rstride = N_ATOMS / 8;
    const uint4* Abase = g_Ab + (size_t)row0 * rstride + kb * (KCHUNK / 8);

    ull acc[MVROWS][5];
#pragma unroll
    for (int r = 0; r < MVROWS; r++)
#pragma unroll
        for (int p = 0; p < 5; p++) acc[r][p] = 0ull;

    for (int it = 0; it < KCHUNK / 256; it++) {
        int q = it * 32 + lane;
        uint4 a[MVROWS];
#pragma unroll
        for (int r = 0; r < MVROWS; r++) a[r] = Abase[r * rstride + q];
#pragma unroll
        for (int k8 = 0; k8 < 8; k8++) {
            ull h[5];
#pragma unroll
            for (int p = 0; p < 5; p++)
                h[p] = sh[(k8 * 5 + p) * (KCHUNK / 8) + q];
#pragma unroll
            for (int r = 0; r < MVROWS; r++) {
                unsigned w = (k8 < 2) ? a[r].x : (k8 < 4) ? a[r].y
                           : (k8 < 6) ? a[r].z : a[r].w;
                float av = (k8 & 1) ? __uint_as_float(w & 0xffff0000u)
                                    : __uint_as_float(w << 16);
                ull v = pack2(av, av);
#pragma unroll
                for (int p = 0; p < 5; p++) fma2(acc[r][p], v, h[p]);
            }
        }
    }

#pragma unroll
    for (int r = 0; r < MVROWS; r++) {
        float f[DD];
#pragma unroll
        for (int p = 0; p < 5; p++) unpack2(acc[r][p], f[2 * p], f[2 * p + 1]);
#pragma unroll
        for (int d = 0; d < DD; d++)
#pragma unroll
            for (int o = 16; o > 0; o >>= 1)
                f[d] += __shfl_down_sync(0xffffffffu, f[d], o);
        if (lane == 0)
#pragma unroll
            for (int d = 0; d < DD; d++) pout[(row0 + r) * DD + d] = f[d];
    }
}

// ---------------- CNN tile: 512 rows, 2 rows/thread ----------------
__device__ __forceinline__ void cnn_tile(char* smem_raw, int t, int layer,
                                         const float* Wc, const float* bc) {
    float* sIn = (float*)smem_raw;
    ull*   sW  = (ull*)(smem_raw + 24000);
    const int tid = threadIdx.x;
    const float* in = g_cnn[layer & 1];
    float*       o  = g_cnn[(layer & 1) ^ 1];
    const float* W  = Wc + layer * KS * KS;
    const float bias = bc[layer];

    for (int i = tid; i < KS * 50; i += NT) {
        int dl = i / 50, rem = i % 50, c = rem / 5, p = rem % 5;
        sW[i] = pack2(W[dl * KS + 11 + c - 2 * p], W[dl * KS + 11 + c - 2 * p - 1]);
    }
    int base = t * 512 - 11;
    for (int i = tid; i < (512 + 22) * DD; i += NT) {
        int rr = i / DD, c = i - rr * DD;
        int g = base + rr;
        sIn[rr * 11 + c] = (g >= 0 && g < L_WORDS) ? in[g * DD + c] : 0.f;
    }
    __syncthreads();

    ull b2 = pack2(bias, bias);
    ull acc[2][5];
#pragma unroll
    for (int r = 0; r < 2; r++)
#pragma unroll
        for (int p = 0; p < 5; p++) acc[r][p] = b2;
#pragma unroll 1
    for (int dl = 0; dl < KS; dl++) {
#pragma unroll
        for (int c = 0; c < DD; c++) {
            ull w[5];
#pragma unroll
            for (int p = 0; p < 5; p++) w[p] = sW[dl * 50 + c * 5 + p];
#pragma unroll
            for (int r = 0; r < 2; r++) {
                float xv = sIn[(tid + r * 256 + dl) * 11 + c];
                ull x2 = pack2(xv, xv);
#pragma unroll
                for (int p = 0; p < 5; p++) fma2(acc[r][p], x2, w[p]);
            }
        }
    }
#pragma unroll
    for (int r = 0; r < 2; r++) {
        int grow = t * 512 + tid + r * 256;
#pragma unroll
        for (int p = 0; p < 5; p++) {
            float v0, v1;
            unpack2(acc[r][p], v0, v1);
            o[grow * DD + 2 * p]     = fmaxf(v0, 0.f);
            o[grow * DD + 2 * p + 1] = fmaxf(v1, 0.f);
        }
    }
}

// ================== the one persistent kernel =================================
__global__ void __launch_bounds__(NT, 2) k_all(
    const int* __restrict__ fp, const float* __restrict__ A,
    const int* __restrict__ words, const float* __restrict__ embf,
    const float* __restrict__ embw,
    const float* __restrict__ Wg, const float* __restrict__ bg,
    const float* __restrict__ Wc, const float* __restrict__ bc,
    const float* __restrict__ Wat, const float* __restrict__ bat,
    const float* __restrict__ Wout, const float* __restrict__ bout,
    const float* __restrict__ Wint, const float* __restrict__ bint,
    float* __restrict__ out)
{
    extern __shared__ char smem_raw[];
    const int tid = threadIdx.x;
    const int bid = blockIdx.x;
    const int nb  = gridDim.x;
    const int cnb = (nb >= 192) ? 128 : nb / 2;   // CNN chain blocks
    const int gnb = nb - cnb;                      // GNN chain blocks

    if (bid < gnb) {
        // =============== GNN chain (private barrier g_barG) ===============
        const int gs = gnb * NT;
        // P0a: fingerprint gather + xs + hs layer0
        for (int m = bid * NT + tid; m < N_ATOMS; m += gs) {
            float x[DD];
#pragma unroll
            for (int c = 0; c < DD; c++) {
                x[c] = embf[(size_t)fp[m] * DD + c];
                g_xs[m * DD + c] = x[c];
            }
            hs_store(m, x, Wg, bg);
        }
        pbar(&g_barG, gnb);

        // layer 0: 256 mv0 tiles (fp32 read, bf16 write)
        for (int u = bid; u < 256; u += gnb) {
            mv0_tile(smem_raw, u, A);
            __syncthreads();
        }
        pbar(&g_barG, gnb);
        // xs += P; hs layer1
        for (int m = bid * NT + tid; m < N_ATOMS; m += gs) {
            float x[DD];
#pragma unroll
            for (int c = 0; c < DD; c++) {
                float v = g_xs[m * DD + c] + g_pp[0][m * DD + c] + g_pp[1][m * DD + c];
                g_xs[m * DD + c] = v;
                x[c] = v;
            }
            hs_store(m, x, Wg + DD * DD, bg + DD);
        }
        pbar(&g_barG, gnb);

        // layer 1: 128 bf16 mv tiles
        for (int u = bid; u < 128; u += gnb) {
            mv_tile(smem_raw, u);
            __syncthreads();
        }
        pbar(&g_barG, gnb);
        // xs += P; hs layer2
        for (int m = bid * NT + tid; m < N_ATOMS; m += gs) {
            float x[DD];
#pragma unroll
            for (int c = 0; c < DD; c++) {
                float v = g_xs[m * DD + c] + g_pp[0][m * DD + c] + g_pp[1][m * DD + c];
                g_xs[m * DD + c] = v;
                x[c] = v;
            }
            hs_store(m, x, Wg + 2 * DD * DD, bg + 2 * DD);
        }
        pbar(&g_barG, gnb);

        // layer 2: 128 bf16 mv tiles
        for (int u = bid; u < 128; u += gnb) {
            mv_tile(smem_raw, u);
            __syncthreads();
        }
        pbar(&g_barG, gnb);

        // compound partials (xs3 = xs2 + P folded)
        {
            float* red = (float*)smem_raw;
            float acc[DD];
#pragma unroll
            for (int d = 0; d < DD; d++) acc[d] = 0.f;
            for (int n = bid * NT + tid; n < N_ATOMS; n += gs)
#pragma unroll
                for (int d = 0; d < DD; d++)
                    acc[d] += g_xs[n * DD + d] + g_pp[0][n * DD + d] + g_pp[1][n * DD + d];
#pragma unroll
            for (int d = 0; d < DD; d++) red[tid * DD + d] = acc[d];
            __syncthreads();
            for (int s = 128; s > 0; s >>= 1) {
                if (tid < s) {
#pragma unroll
                    for (int d = 0; d < DD; d++)
                        red[tid * DD + d] += red[(tid + s) * DD + d];
                }
                __syncthreads();
            }
            if (tid < DD) g_cpart[bid * DD + tid] = red[tid];
        }
    } else {
        // =============== CNN chain (private barrier g_barC) ===============
        const int cbid = bid - gnb;
        const int cs = cnb * NT;
        // word gather
        for (int i = cbid * NT + tid; i < L_WORDS * DD; i += cs) {
            int n = i / DD, d = i - n * DD;
            g_cnn[0][i] = embw[(size_t)words[n] * DD + d];
        }
        pbar(&g_barC, cnb);
        for (int layer = 0; layer < 3; layer++) {
            for (int t = cbid; t < 128; t += cnb) {
                cnn_tile(smem_raw, t, layer, Wc, bc);
                __syncthreads();
            }
            pbar(&g_barC, cnb);
        }
    }

    // =============== join ===============
    pbar(&g_bar, nb);

    // ---------- redundant compound finalize + attention (all blocks) ----------
    {
        float* sWat = (float*)smem_raw;
        float* sbv  = sWat + DD * DD;
        float* shv  = sbv + DD;
        float* red  = shv + DD + 2;
        if (tid < DD * DD) sWat[tid] = Wat[tid];
        if (tid < DD) {
            float s = 0.f;
            for (int b = 0; b < gnb; b++) s += g_cpart[b * DD + tid];
            float comp = s * (1.f / N_ATOMS);
            if (bid == 0) g_comp[tid] = comp;
            sbv[tid] = bat[tid];
            red[tid] = comp;
        }
        __syncthreads();
        if (tid < DD) {
            float hv = sbv[tid];
#pragma unroll
            for (int c = 0; c < DD; c++) hv = fmaf(red[c], sWat[tid * DD + c], hv);
            shv[tid] = fmaxf(hv, 0.f);
        }
        __syncthreads();

        float acc[DD];
#pragma unroll
        for (int d = 0; d < DD; d++) acc[d] = 0.f;
        const float* in = g_cnn[1];
        for (int l = bid * NT + tid; l < L_WORDS; l += nb * NT) {
            float x[DD];
#pragma unroll
            for (int c = 0; c < DD; c++) x[c] = in[l * DD + c];
            float hp[DD], wl = 0.f;
#pragma unroll
            for (int u = 0; u < DD; u++) {
                float v = sbv[u];
#pragma unroll
                for (int c = 0; c < DD; c++) v = fmaf(x[c], sWat[u * DD + c], v);
                v = fmaxf(v, 0.f);
                hp[u] = v;
                wl = fmaf(shv[u], v, wl);
            }
            wl = tanhf(wl);
#pragma unroll
            for (int d = 0; d < DD; d++) acc[d] = fmaf(wl, hp[d], acc[d]);
        }
        __syncthreads();
#pragma unroll
        for (int d = 0; d < DD; d++) red[tid * DD + d] = acc[d];
        __syncthreads();
        for (int s = 128; s > 0; s >>= 1) {
            if (tid < s) {
#pragma unroll
                for (int d = 0; d < DD; d++)
                    red[tid * DD + d] += red[(tid + s) * DD + d];
            }
            __syncthreads();
        }
        if (tid < DD) g_part[bid * DD + tid] = red[tid];
    }
    pbar(&g_bar, nb);

    // ---------- final: reduce g_part + fusion MLP (block 0) ----------
    if (bid == 0) {
        float* red = (float*)smem_raw;
        float* cat = red + NT * DD;
        float acc[DD];
#pragma unroll
        for (int d = 0; d < DD; d++) acc[d] = 0.f;
        for (int b = tid; b < nb; b += NT)
#pragma unroll
            for (int d = 0; d < DD; d++) acc[d] += g_part[b * DD + d];
#pragma unroll
        for (int d = 0; d < DD; d++) red[tid * DD + d] = acc[d];
        __syncthreads();
        for (int s = 128; s > 0; s >>= 1) {
            if (tid < s) {
#pragma unroll
                for (int d = 0; d < DD; d++)
                    red[tid * DD + d] += red[(tid + s) * DD + d];
            }
            __syncthreads();
        }
        if (tid < DD) cat[tid] = g_comp[tid];
        if (tid >= DD && tid < 20) cat[tid] = red[tid - DD] * (1.f / L_WORDS);
        __syncthreads();
        if (tid < 32) {
            for (int j = 0; j < 3; j++) {
                float v = 0.f;
                if (tid < 20) {
                    v = bout[j * 20 + tid];
                    for (int c = 0; c < 20; c++)
                        v = fmaf(cat[c], Wout[j * 400 + tid * 20 + c], v);
                    v = fmaxf(v, 0.f);
                }
                __syncwarp();
                if (tid < 20) cat[tid] = v;
                __syncwarp();
            }
            if (tid < 2) {
                float v = bint[tid];
                for (int c = 0; c < 20; c++) v = fmaf(cat[c], Wint[tid * 20 + c], v);
                out[tid] = v;
            }
        }
    }
}

// ---------------- launch ------------------------------------------------------
extern "C" void kernel_launch(void* const* d_in, const int* in_sizes, int n_in,
                              void* d_out, int out_size) {
    const int*   fp    = (const int*)d_in[0];
    const float* A     = (const float*)d_in[1];
    const int*   words = (const int*)d_in[2];
    const float* embf  = (const float*)d_in[3];
    const float* embw  = (const float*)d_in[4];
    const float* Wg    = (const float*)d_in[5];
    const float* bg    = (const float*)d_in[6];
    const float* Wc    = (const float*)d_in[7];
    const float* bc    = (const float*)d_in[8];
    const float* Wat   = (const float*)d_in[9];
    const float* bat   = (const float*)d_in[10];
    const float* Wout  = (const float*)d_in[11];
    const float* bout  = (const float*)d_in[12];
    const float* Wint  = (const float*)d_in[13];
    const float* bint  = (const float*)d_in[14];
    float* out = (float*)d_out;

    cudaFuncSetAttribute(k_all, cudaFuncAttributeMaxDynamicSharedMemorySize, SMEM_BYTES);
    int dev = 0;
    cudaGetDevice(&dev);
    int nsm = 0;
    cudaDeviceGetAttribute(&nsm, cudaDevAttrMultiProcessorCount, dev);
    int per = 0;
    cudaOccupancyMaxActiveBlocksPerMultiprocessor(&per, k_all, NT, SMEM_BYTES);
    if (per < 1) per = 1;
    if (per > 2) per = 2;
    int grid = nsm * per;

    k_all<<<grid, NT, SMEM_BYTES>>>(fp, A, words, embf, embw, Wg, bg, Wc, bc,
                                    Wat, bat, Wout, bout, Wint, bint, out);
}

// round 10
// speedup vs baseline: 1.2225x; 1.2225x over previous
#include <cuda_runtime.h>
#include <cstdint>

#define N_ATOMS 4096
#define L_WORDS 65536
#define DD 10
#define KS 23
#define KSPLIT 2
#define KCHUNK (N_ATOMS / KSPLIT)   // 2048
#define NT 256
#define SMEM_BYTES 81920            // 40 * (KCHUNK/8) * 8
#define MVROWS 4
#define MVTILE 32                   // 8 warps * 4 rows

typedef unsigned long long ull;

// ---------------- scratch ----------------
__device__ float g_xs[N_ATOMS * DD];
__device__ ull   g_hs[8 * 5 * (N_ATOMS / 8)];        // hs f32x2, [k8][p][m/8]
__device__ uint4 g_Ab[(size_t)N_ATOMS * N_ATOMS / 8];
__device__ float g_pp[KSPLIT][N_ATOMS * DD];
__device__ float g_cnn[2][L_WORDS * DD];
__device__ float g_comp[DD];
__device__ float g_hatt[DD];
__device__ float g_part[256 * DD];

// ---------------- helpers ----------------
__device__ __forceinline__ ull pack2(float x, float y) {
    ull r; asm("mov.b64 %0, {%1, %2};" : "=l"(r) : "f"(x), "f"(y)); return r;
}
__device__ __forceinline__ void unpack2(ull v, float& x, float& y) {
    asm("mov.b64 {%0, %1}, %2;" : "=f"(x), "=f"(y) : "l"(v));
}
__device__ __forceinline__ void fma2(ull& d, ull a, ull b) {
    asm("fma.rn.f32x2 %0, %1, %2, %0;" : "+l"(d) : "l"(a), "l"(b));
}
__device__ __forceinline__ unsigned bfpack(float lo, float hi) {
    unsigned r;
    asm("cvt.rn.bf16x2.f32 %0, %1, %2;" : "=r"(r) : "f"(hi), "f"(lo));
    return r;
}

__device__ __forceinline__ void hs_store(int m, const float* x,
                                         const float* Wgl, const float* bgl) {
    int k8 = m & 7, base = m >> 3;
#pragma unroll
    for (int p = 0; p < 5; p++) {
        float h0 = bgl[2 * p], h1 = bgl[2 * p + 1];
#pragma unroll
        for (int c = 0; c < DD; c++) {
            h0 = fmaf(x[c], Wgl[(2 * p) * DD + c], h0);
            h1 = fmaf(x[c], Wgl[(2 * p + 1) * DD + c], h1);
        }
        g_hs[(k8 * 5 + p) * (N_ATOMS / 8) + base] =
            pack2(fmaxf(h0, 0.f), fmaxf(h1, 0.f));
    }
}

__device__ __forceinline__ void fill_hs(ull* sh, int kb) {
    for (int i = threadIdx.x; i < 40 * (KCHUNK / 8); i += NT) {
        int kp = i / (KCHUNK / 8), j = i % (KCHUNK / 8);
        sh[i] = g_hs[kp * (N_ATOMS / 8) + kb * (KCHUNK / 8) + j];
    }
    __syncthreads();
}

// ---------------- GNN chain kernels ----------------
// pre: fingerprint gather + xs + hs layer0
__global__ void __launch_bounds__(NT) k_pre(const int* __restrict__ fp,
                                            const float* __restrict__ embf,
                                            const float* __restrict__ Wg,
                                            const float* __restrict__ bg) {
    int m = blockIdx.x * NT + threadIdx.x;
    float x[DD];
#pragma unroll
    for (int c = 0; c < DD; c++) {
        x[c] = embf[(size_t)fp[m] * DD + c];
        g_xs[m * DD + c] = x[c];
    }
    hs_store(m, x, Wg, bg);
}

// xs += P0+P1; hs for given layer
__global__ void __launch_bounds__(NT) k_hs(const float* __restrict__ Wgl,
                                           const float* __restrict__ bgl) {
    int m = blockIdx.x * NT + threadIdx.x;
    float x[DD];
#pragma unroll
    for (int c = 0; c < DD; c++) {
        float v = g_xs[m * DD + c] + g_pp[0][m * DD + c] + g_pp[1][m * DD + c];
        g_xs[m * DD + c] = v;
        x[c] = v;
    }
    hs_store(m, x, Wgl, bgl);
}

// layer0 mv: fp32 A read, bf16 write, 32-row tiles, grid 256
__global__ void __launch_bounds__(NT, 2) k_mv0(const float* __restrict__ A) {
    extern __shared__ char smem_raw[];
    ull* sh = (ull*)smem_raw;
    const int tid = threadIdx.x;
    const int rowblk = blockIdx.x & 127, kb = blockIdx.x >> 7;
    fill_hs(sh, kb);

    const int warp = tid >> 5, lane = tid & 31;
    const int row0 = rowblk * MVTILE + warp * MVROWS;
    float* pout = g_pp[kb];

    const float4* Af[MVROWS];
    uint4* Ao[MVROWS];
#pragma unroll
    for (int r = 0; r < MVROWS; r++) {
        Af[r] = (const float4*)A + (size_t)(row0 + r) * (N_ATOMS / 4) + kb * (KCHUNK / 4);
        Ao[r] = g_Ab + (size_t)(row0 + r) * (N_ATOMS / 8) + kb * (KCHUNK / 8);
    }

    ull acc[MVROWS][5];
#pragma unroll
    for (int r = 0; r < MVROWS; r++)
#pragma unroll
        for (int p = 0; p < 5; p++) acc[r][p] = 0ull;

    for (int it = 0; it < KCHUNK / 256; it++) {
        int q = it * 32 + lane;
        float4 lo[MVROWS], hi[MVROWS];
#pragma unroll
        for (int r = 0; r < MVROWS; r++) {
            lo[r] = Af[r][2 * q];
            hi[r] = Af[r][2 * q + 1];
            uint4 o;
            o.x = bfpack(lo[r].x, lo[r].y);
            o.y = bfpack(lo[r].z, lo[r].w);
            o.z = bfpack(hi[r].x, hi[r].y);
            o.w = bfpack(hi[r].z, hi[r].w);
            Ao[r][q] = o;
        }
#pragma unroll
        for (int k8 = 0; k8 < 8; k8++) {
            ull h[5];
#pragma unroll
            for (int p = 0; p < 5; p++)
                h[p] = sh[(k8 * 5 + p) * (KCHUNK / 8) + q];
#pragma unroll
            for (int r = 0; r < MVROWS; r++) {
                float av = (k8 == 0) ? lo[r].x : (k8 == 1) ? lo[r].y
                         : (k8 == 2) ? lo[r].z : (k8 == 3) ? lo[r].w
                         : (k8 == 4) ? hi[r].x : (k8 == 5) ? hi[r].y
                         : (k8 == 6) ? hi[r].z : hi[r].w;
                ull v = pack2(av, av);
#pragma unroll
                for (int p = 0; p < 5; p++) fma2(acc[r][p], v, h[p]);
            }
        }
    }

#pragma unroll
    for (int r = 0; r < MVROWS; r++) {
        float f[DD];
#pragma unroll
        for (int p = 0; p < 5; p++) unpack2(acc[r][p], f[2 * p], f[2 * p + 1]);
#pragma unroll
        for (int d = 0; d < DD; d++)
#pragma unroll
            for (int o = 16; o > 0; o >>= 1)
                f[d] += __shfl_down_sync(0xffffffffu, f[d], o);
        if (lane == 0)
#pragma unroll
            for (int d = 0; d < DD; d++) pout[(row0 + r) * DD + d] = f[d];
    }
}

// layers 1,2 mv: bf16 A with prefetch, 32-row tiles, grid 256
__global__ void __launch_bounds__(NT, 2) k_mv() {
    extern __shared__ char smem_raw[];
    ull* sh = (ull*)smem_raw;
    const int tid = threadIdx.x;
    const int rowblk = blockIdx.x & 127, kb = blockIdx.x >> 7;
    fill_hs(sh, kb);

    const int warp = tid >> 5, lane = tid & 31;
    const int row0 = rowblk * MVTILE + warp * MVROWS;
    float* pout = g_pp[kb];
    const int rstride = N_ATOMS / 8;
    const uint4* Abase = g_Ab + (size_t)row0 * rstride + kb * (KCHUNK / 8);

    ull acc[MVROWS][5];
#pragma unroll
    for (int r = 0; r < MVROWS; r++)
#pragma unroll
        for (int p = 0; p < 5; p++) acc[r][p] = 0ull;

    uint4 a[MVROWS];
#pragma unroll
    for (int r = 0; r < MVROWS; r++) a[r] = Abase[r * rstride + lane];

    for (int it = 0; it < KCHUNK / 256; it++) {
        int q = it * 32 + lane;
        uint4 nxt[MVROWS];
        if (it + 1 < KCHUNK / 256) {
#pragma unroll
            for (int r = 0; r < MVROWS; r++) nxt[r] = Abase[r * rstride + q + 32];
        }
#pragma unroll
        for (int k8 = 0; k8 < 8; k8++) {
            ull h[5];
#pragma unroll
            for (int p = 0; p < 5; p++)
                h[p] = sh[(k8 * 5 + p) * (KCHUNK / 8) + q];
#pragma unroll
            for (int r = 0; r < MVROWS; r++) {
                unsigned w = (k8 < 2) ? a[r].x : (k8 < 4) ? a[r].y
                           : (k8 < 6) ? a[r].z : a[r].w;
                float av = (k8 & 1) ? __uint_as_float(w & 0xffff0000u)
                                    : __uint_as_float(w << 16);
                ull v = pack2(av, av);
#pragma unroll
                for (int p = 0; p < 5; p++) fma2(acc[r][p], v, h[p]);
            }
        }
#pragma unroll
        for (int r = 0; r < MVROWS; r++) a[r] = nxt[r];
    }

#pragma unroll
    for (int r = 0; r < MVROWS; r++) {
        float f[DD];
#pragma unroll
        for (int p = 0; p < 5; p++) unpack2(acc[r][p], f[2 * p], f[2 * p + 1]);
#pragma unroll
        for (int d = 0; d < DD; d++)
#pragma unroll
            for (int o = 16; o > 0; o >>= 1)
                f[d] += __shfl_down_sync(0xffffffffu, f[d], o);
        if (lane == 0)
#pragma unroll
            for (int d = 0; d < DD; d++) pout[(row0 + r) * DD + d] = f[d];
    }
}

// compound = mean(xs + P0 + P1); hatt = relu(comp@Wat^T + bat)
__global__ void __launch_bounds__(512) k_comp(const float* __restrict__ Wat,
                                              const float* __restrict__ bat) {
    __shared__ float red[512 * DD];
    int tid = threadIdx.x;
    float acc[DD];
#pragma unroll
    for (int d = 0; d < DD; d++) acc[d] = 0.f;
    for (int n = tid; n < N_ATOMS; n += 512)
#pragma unroll
        for (int d = 0; d < DD; d++)
            acc[d] += g_xs[n * DD + d] + g_pp[0][n * DD + d] + g_pp[1][n * DD + d];
#pragma unroll
    for (int d = 0; d < DD; d++) red[tid * DD + d] = acc[d];
    __syncthreads();
    for (int s = 256; s > 0; s >>= 1) {
        if (tid < s) {
#pragma unroll
            for (int d = 0; d < DD; d++) red[tid * DD + d] += red[(tid + s) * DD + d];
        }
        __syncthreads();
    }
    if (tid < DD) {
        float comp = red[tid] * (1.f / N_ATOMS);
        g_comp[tid] = comp;
        float hv = bat[tid];
#pragma unroll
        for (int c = 0; c < DD; c++)
            hv = fmaf(red[c] * (1.f / N_ATOMS), Wat[tid * DD + c], hv);
        g_hatt[tid] = fmaxf(hv, 0.f);
    }
}

// ---------------- CNN chain kernels ----------------
__global__ void __launch_bounds__(NT) k_gather_w(const int* __restrict__ wd,
                                                 const float* __restrict__ emb) {
    int i = blockIdx.x * NT + threadIdx.x;
    int n = i / DD, d = i - n * DD;
    g_cnn[0][i] = emb[(size_t)wd[n] * DD + d];
}

// one conv layer, 256-row tiles, 1 row/thread, grid 256
__global__ void __launch_bounds__(NT) k_cnn(int layer, const float* __restrict__ Wc,
                                            const float* __restrict__ bc) {
    __shared__ float sIn[(NT + 22) * 11];
    __shared__ ull sW[KS * 50];
    const int tid = threadIdx.x;
    const float* in = g_cnn[layer & 1];
    float*       o  = g_cnn[(layer & 1) ^ 1];
    const float* W  = Wc + layer * KS * KS;
    const float bias = bc[layer];

    for (int i = tid; i < KS * 50; i += NT) {
        int dl = i / 50, rem = i % 50, c = rem / 5, p = rem % 5;
        sW[i] = pack2(W[dl * KS + 11 + c - 2 * p], W[dl * KS + 11 + c - 2 * p - 1]);
    }
    int base = blockIdx.x * NT - 11;
    for (int i = tid; i < (NT + 22) * DD; i += NT) {
        int rr = i / DD, c = i - rr * DD;
        int g = base + rr;
        sIn[rr * 11 + c] = (g >= 0 && g < L_WORDS) ? in[g * DD + c] : 0.f;
    }
    __syncthreads();

    ull b2 = pack2(bias, bias);
    ull acc[5];
#pragma unroll
    for (int p = 0; p < 5; p++) acc[p] = b2;
#pragma unroll 1
    for (int dl = 0; dl < KS; dl++) {
#pragma unroll
        for (int c = 0; c < DD; c++) {
            float xv = sIn[(tid + dl) * 11 + c];
            ull x2 = pack2(xv, xv);
#pragma unroll
            for (int p = 0; p < 5; p++) fma2(acc[p], x2, sW[dl * 50 + c * 5 + p]);
        }
    }
    int grow = blockIdx.x * NT + tid;
#pragma unroll
    for (int p = 0; p < 5; p++) {
        float v0, v1;
        unpack2(acc[p], v0, v1);
        o[grow * DD + 2 * p]     = fmaxf(v0, 0.f);
        o[grow * DD + 2 * p + 1] = fmaxf(v1, 0.f);
    }
}

// ---------------- join kernels ----------------
__global__ void __launch_bounds__(NT) k_att(const float* __restrict__ Wat,
                                            const float* __restrict__ bat) {
    __shared__ float sWat[DD * DD], sbv[DD], shv[DD];
    __shared__ float red[NT * DD];
    const int tid = threadIdx.x;
    if (tid < DD * DD) sWat[tid] = Wat[tid];
    if (tid < DD) { sbv[tid] = bat[tid]; shv[tid] = g_hatt[tid]; }
    __syncthreads();

    int l = blockIdx.x * NT + tid;
    const float* in = g_cnn[1];
    float x[DD];
#pragma unroll
    for (int c = 0; c < DD; c++) x[c] = in[l * DD + c];
    float hp[DD], wl = 0.f;
#pragma unroll
    for (int u = 0; u < DD; u++) {
        float v = sbv[u];
#pragma unroll
        for (int c = 0; c < DD; c++) v = fmaf(x[c], sWat[u * DD + c], v);
        v = fmaxf(v, 0.f);
        hp[u] = v;
        wl = fmaf(shv[u], v, wl);
    }
    wl = tanhf(wl);
#pragma unroll
    for (int d = 0; d < DD; d++) red[tid * DD + d] = wl * hp[d];
    __syncthreads();
    for (int s = 128; s > 0; s >>= 1) {
        if (tid < s) {
#pragma unroll
            for (int d = 0; d < DD; d++) red[tid * DD + d] += red[(tid + s) * DD + d];
        }
        __syncthreads();
    }
    if (tid < DD) g_part[blockIdx.x * DD + tid] = red[tid];
}

__global__ void __launch_bounds__(NT) k_final(const float* __restrict__ Wout,
                                              const float* __restrict__ bout,
                                              const float* __restrict__ Wint,
                                              const float* __restrict__ bint,
                                              float* __restrict__ out) {
    __shared__ float red[NT * DD];
    __shared__ float cat[20];
    const int tid = threadIdx.x;
#pragma unroll
    for (int d = 0; d < DD; d++) red[tid * DD + d] = g_part[tid * DD + d];
    __syncthreads();
    for (int s = 128; s > 0; s >>= 1) {
        if (tid < s) {
#pragma unroll
            for (int d = 0; d < DD; d++) red[tid * DD + d] += red[(tid + s) * DD + d];
        }
        __syncthreads();
    }
    if (tid < DD) cat[tid] = g_comp[tid];
    if (tid >= DD && tid < 20) cat[tid] = red[tid - DD] * (1.f / L_WORDS);
    __syncthreads();
    if (tid < 32) {
        for (int j = 0; j < 3; j++) {
            float v = 0.f;
            if (tid < 20) {
                v = bout[j * 20 + tid];
                for (int c = 0; c < 20; c++)
                    v = fmaf(cat[c], Wout[j * 400 + tid * 20 + c], v);
                v = fmaxf(v, 0.f);
            }
            __syncwarp();
            if (tid < 20) cat[tid] = v;
            __syncwarp();
        }
        if (tid < 2) {
            float v = bint[tid];
            for (int c = 0; c < 20; c++) v = fmaf(cat[c], Wint[tid * 20 + c], v);
            out[tid] = v;
        }
    }
}

// ---------------- launch: graph with two parallel branches ----------------
extern "C" void kernel_launch(void* const* d_in, const int* in_sizes, int n_in,
                              void* d_out, int out_size) {
    const int*   fp    = (const int*)d_in[0];
    const float* A     = (const float*)d_in[1];
    const int*   words = (const int*)d_in[2];
    const float* embf  = (const float*)d_in[3];
    const float* embw  = (const float*)d_in[4];
    const float* Wg    = (const float*)d_in[5];
    const float* bg    = (const float*)d_in[6];
    const float* Wc    = (const float*)d_in[7];
    const float* bc    = (const float*)d_in[8];
    const float* Wat   = (const float*)d_in[9];
    const float* bat   = (const float*)d_in[10];
    const float* Wout  = (const float*)d_in[11];
    const float* bout  = (const float*)d_in[12];
    const float* Wint  = (const float*)d_in[13];
    const float* bint  = (const float*)d_in[14];
    float* out = (float*)d_out;

    cudaFuncSetAttribute(k_mv0, cudaFuncAttributeMaxDynamicSharedMemorySize, SMEM_BYTES);
    cudaFuncSetAttribute(k_mv,  cudaFuncAttributeMaxDynamicSharedMemorySize, SMEM_BYTES);

    // fork a second stream for the CNN chain (host-side cost is capture-time
    // only; the resulting graph has two parallel branches). Streams/events are
    // intentionally not destroyed here: destroying a stream that participated
    // in an active capture invalidates it. kernel_launch is called twice total.
    cudaStream_t sC;
    cudaStreamCreateWithFlags(&sC, cudaStreamNonBlocking);
    cudaEvent_t eFork, eJoin;
    cudaEventCreateWithFlags(&eFork, cudaEventDisableTiming);
    cudaEventCreateWithFlags(&eJoin, cudaEventDisableTiming);

    cudaEventRecord(eFork, 0);
    cudaStreamWaitEvent(sC, eFork, 0);

    // ----- CNN branch (stream sC) -----
    k_gather_w<<<L_WORDS * DD / NT, NT, 0, sC>>>(words, embw);
    k_cnn<<<L_WORDS / NT, NT, 0, sC>>>(0, Wc, bc);
    k_cnn<<<L_WORDS / NT, NT, 0, sC>>>(1, Wc, bc);
    k_cnn<<<L_WORDS / NT, NT, 0, sC>>>(2, Wc, bc);
    cudaEventRecord(eJoin, sC);

    // ----- GNN branch (capture stream) -----
    k_pre<<<N_ATOMS / NT, NT>>>(fp, embf, Wg, bg);
    k_mv0<<<256, NT, SMEM_BYTES>>>(A);
    k_hs<<<N_ATOMS / NT, NT>>>(Wg + DD * DD, bg + DD);
    k_mv<<<256, NT, SMEM_BYTES>>>();
    k_hs<<<N_ATOMS / NT, NT>>>(Wg + 2 * DD * DD, bg + 2 * DD);
    k_mv<<<256, NT, SMEM_BYTES>>>();
    k_comp<<<1, 512>>>(Wat, bat);

    // ----- join + tail -----
    cudaStreamWaitEvent(0, eJoin, 0);
    k_att<<<L_WORDS / NT, NT>>>(Wat, bat);
    k_final<<<1, NT>>>(Wout, bout, Wint, bint, out);
}

// round 11
// speedup vs baseline: 1.2687x; 1.0378x over previous
#include <cuda_runtime.h>
#include <cstdint>

#define N_ATOMS 4096
#define L_WORDS 65536
#define DD 10
#define KS 23
#define KSPLIT 2
#define KCHUNK (N_ATOMS / KSPLIT)   // 2048
#define NT 256
#define SMEM_BYTES 81920            // 40 * (KCHUNK/8) * 8
#define MVROWS 4
#define MVTILE 32                   // 8 warps * 4 rows
#define CROWS 128                   // rows per CNN block (2 threads/row)

typedef unsigned long long ull;

// ---------------- scratch ----------------
__device__ float g_xs[N_ATOMS * DD];
__device__ ull   g_hs[8 * 5 * (N_ATOMS / 8)];        // hs f32x2, [k8][p][m/8]
__device__ uint4 g_Ab[(size_t)N_ATOMS * N_ATOMS / 8];
__device__ float g_pp[KSPLIT][N_ATOMS * DD];
__device__ float g_cnn[2][L_WORDS * DD];
__device__ float g_comp[DD];
__device__ float g_hatt[DD];
__device__ float g_part[256 * DD];

// ---------------- helpers ----------------
__device__ __forceinline__ ull pack2(float x, float y) {
    ull r; asm("mov.b64 %0, {%1, %2};" : "=l"(r) : "f"(x), "f"(y)); return r;
}
__device__ __forceinline__ void unpack2(ull v, float& x, float& y) {
    asm("mov.b64 {%0, %1}, %2;" : "=f"(x), "=f"(y) : "l"(v));
}
__device__ __forceinline__ void fma2(ull& d, ull a, ull b) {
    asm("fma.rn.f32x2 %0, %1, %2, %0;" : "+l"(d) : "l"(a), "l"(b));
}
__device__ __forceinline__ ull add2(ull a, ull b) {
    ull r; asm("add.rn.f32x2 %0, %1, %2;" : "=l"(r) : "l"(a), "l"(b)); return r;
}
__device__ __forceinline__ unsigned bfpack(float lo, float hi) {
    unsigned r;
    asm("cvt.rn.bf16x2.f32 %0, %1, %2;" : "=r"(r) : "f"(hi), "f"(lo));
    return r;
}

__device__ __forceinline__ void hs_store(int m, const float* x,
                                         const float* Wgl, const float* bgl) {
    int k8 = m & 7, base = m >> 3;
#pragma unroll
    for (int p = 0; p < 5; p++) {
        float h0 = bgl[2 * p], h1 = bgl[2 * p + 1];
#pragma unroll
        for (int c = 0; c < DD; c++) {
            h0 = fmaf(x[c], Wgl[(2 * p) * DD + c], h0);
            h1 = fmaf(x[c], Wgl[(2 * p + 1) * DD + c], h1);
        }
        g_hs[(k8 * 5 + p) * (N_ATOMS / 8) + base] =
            pack2(fmaxf(h0, 0.f), fmaxf(h1, 0.f));
    }
}

__device__ __forceinline__ void fill_hs(ull* sh, int kb) {
    for (int i = threadIdx.x; i < 40 * (KCHUNK / 8); i += NT) {
        int kp = i / (KCHUNK / 8), j = i % (KCHUNK / 8);
        sh[i] = g_hs[kp * (N_ATOMS / 8) + kb * (KCHUNK / 8) + j];
    }
    __syncthreads();
}

// ---------------- GNN chain kernels ----------------
__global__ void __launch_bounds__(NT) k_pre(const int* __restrict__ fp,
                                            const float* __restrict__ embf,
                                            const float* __restrict__ Wg,
                                            const float* __restrict__ bg) {
    int m = blockIdx.x * NT + threadIdx.x;
    float x[DD];
#pragma unroll
    for (int c = 0; c < DD; c++) {
        x[c] = embf[(size_t)fp[m] * DD + c];
        g_xs[m * DD + c] = x[c];
    }
    hs_store(m, x, Wg, bg);
}

__global__ void __launch_bounds__(NT) k_hs(const float* __restrict__ Wgl,
                                           const float* __restrict__ bgl) {
    int m = blockIdx.x * NT + threadIdx.x;
    float x[DD];
#pragma unroll
    for (int c = 0; c < DD; c++) {
        float v = g_xs[m * DD + c] + g_pp[0][m * DD + c] + g_pp[1][m * DD + c];
        g_xs[m * DD + c] = v;
        x[c] = v;
    }
    hs_store(m, x, Wgl, bgl);
}

// layer0 mv: fp32 A read, bf16 write, 32-row tiles, grid 256
__global__ void __launch_bounds__(NT, 2) k_mv0(const float* __restrict__ A) {
    extern __shared__ char smem_raw[];
    ull* sh = (ull*)smem_raw;
    const int tid = threadIdx.x;
    const int rowblk = blockIdx.x & 127, kb = blockIdx.x >> 7;
    fill_hs(sh, kb);

    const int warp = tid >> 5, lane = tid & 31;
    const int row0 = rowblk * MVTILE + warp * MVROWS;
    float* pout = g_pp[kb];

    const float4* Af[MVROWS];
    uint4* Ao[MVROWS];
#pragma unroll
    for (int r = 0; r < MVROWS; r++) {
        Af[r] = (const float4*)A + (size_t)(row0 + r) * (N_ATOMS / 4) + kb * (KCHUNK / 4);
        Ao[r] = g_Ab + (size_t)(row0 + r) * (N_ATOMS / 8) + kb * (KCHUNK / 8);
    }

    ull acc[MVROWS][5];
#pragma unroll
    for (int r = 0; r < MVROWS; r++)
#pragma unroll
        for (int p = 0; p < 5; p++) acc[r][p] = 0ull;

    for (int it = 0; it < KCHUNK / 256; it++) {
        int q = it * 32 + lane;
        float4 lo[MVROWS], hi[MVROWS];
#pragma unroll
        for (int r = 0; r < MVROWS; r++) {
            lo[r] = Af[r][2 * q];
            hi[r] = Af[r][2 * q + 1];
            uint4 o;
            o.x = bfpack(lo[r].x, lo[r].y);
            o.y = bfpack(lo[r].z, lo[r].w);
            o.z = bfpack(hi[r].x, hi[r].y);
            o.w = bfpack(hi[r].z, hi[r].w);
            Ao[r][q] = o;
        }
#pragma unroll
        for (int k8 = 0; k8 < 8; k8++) {
            ull h[5];
#pragma unroll
            for (int p = 0; p < 5; p++)
                h[p] = sh[(k8 * 5 + p) * (KCHUNK / 8) + q];
#pragma unroll
            for (int r = 0; r < MVROWS; r++) {
                float av = (k8 == 0) ? lo[r].x : (k8 == 1) ? lo[r].y
                         : (k8 == 2) ? lo[r].z : (k8 == 3) ? lo[r].w
                         : (k8 == 4) ? hi[r].x : (k8 == 5) ? hi[r].y
                         : (k8 == 6) ? hi[r].z : hi[r].w;
                ull v = pack2(av, av);
#pragma unroll
                for (int p = 0; p < 5; p++) fma2(acc[r][p], v, h[p]);
            }
        }
    }

#pragma unroll
    for (int r = 0; r < MVROWS; r++) {
        float f[DD];
#pragma unroll
        for (int p = 0; p < 5; p++) unpack2(acc[r][p], f[2 * p], f[2 * p + 1]);
#pragma unroll
        for (int d = 0; d < DD; d++)
#pragma unroll
            for (int o = 16; o > 0; o >>= 1)
                f[d] += __shfl_down_sync(0xffffffffu, f[d], o);
        if (lane == 0)
#pragma unroll
            for (int d = 0; d < DD; d++) pout[(row0 + r) * DD + d] = f[d];
    }
}

// layers 1,2 mv: bf16 A with prefetch, 32-row tiles, grid 256
__global__ void __launch_bounds__(NT, 2) k_mv() {
    extern __shared__ char smem_raw[];
    ull* sh = (ull*)smem_raw;
    const int tid = threadIdx.x;
    const int rowblk = blockIdx.x & 127, kb = blockIdx.x >> 7;
    fill_hs(sh, kb);

    const int warp = tid >> 5, lane = tid & 31;
    const int row0 = rowblk * MVTILE + warp * MVROWS;
    float* pout = g_pp[kb];
    const int rstride = N_ATOMS / 8;
    const uint4* Abase = g_Ab + (size_t)row0 * rstride + kb * (KCHUNK / 8);

    ull acc[MVROWS][5];
#pragma unroll
    for (int r = 0; r < MVROWS; r++)
#pragma unroll
        for (int p = 0; p < 5; p++) acc[r][p] = 0ull;

    uint4 a[MVROWS];
#pragma unroll
    for (int r = 0; r < MVROWS; r++) a[r] = Abase[r * rstride + lane];

    for (int it = 0; it < KCHUNK / 256; it++) {
        int q = it * 32 + lane;
        uint4 nxt[MVROWS];
        if (it + 1 < KCHUNK / 256) {
#pragma unroll
            for (int r = 0; r < MVROWS; r++) nxt[r] = Abase[r * rstride + q + 32];
        }
#pragma unroll
        for (int k8 = 0; k8 < 8; k8++) {
            ull h[5];
#pragma unroll
            for (int p = 0; p < 5; p++)
                h[p] = sh[(k8 * 5 + p) * (KCHUNK / 8) + q];
#pragma unroll
            for (int r = 0; r < MVROWS; r++) {
                unsigned w = (k8 < 2) ? a[r].x : (k8 < 4) ? a[r].y
                           : (k8 < 6) ? a[r].z : a[r].w;
                float av = (k8 & 1) ? __uint_as_float(w & 0xffff0000u)
                                    : __uint_as_float(w << 16);
                ull v = pack2(av, av);
#pragma unroll
                for (int p = 0; p < 5; p++) fma2(acc[r][p], v, h[p]);
            }
        }
#pragma unroll
        for (int r = 0; r < MVROWS; r++) a[r] = nxt[r];
    }

#pragma unroll
    for (int r = 0; r < MVROWS; r++) {
        float f[DD];
#pragma unroll
        for (int p = 0; p < 5; p++) unpack2(acc[r][p], f[2 * p], f[2 * p + 1]);
#pragma unroll
        for (int d = 0; d < DD; d++)
#pragma unroll
            for (int o = 16; o > 0; o >>= 1)
                f[d] += __shfl_down_sync(0xffffffffu, f[d], o);
        if (lane == 0)
#pragma unroll
            for (int d = 0; d < DD; d++) pout[(row0 + r) * DD + d] = f[d];
    }
}

__global__ void __launch_bounds__(512) k_comp(const float* __restrict__ Wat,
                                              const float* __restrict__ bat) {
    __shared__ float red[512 * DD];
    int tid = threadIdx.x;
    float acc[DD];
#pragma unroll
    for (int d = 0; d < DD; d++) acc[d] = 0.f;
    for (int n = tid; n < N_ATOMS; n += 512)
#pragma unroll
        for (int d = 0; d < DD; d++)
            acc[d] += g_xs[n * DD + d] + g_pp[0][n * DD + d] + g_pp[1][n * DD + d];
#pragma unroll
    for (int d = 0; d < DD; d++) red[tid * DD + d] = acc[d];
    __syncthreads();
    for (int s = 256; s > 0; s >>= 1) {
        if (tid < s) {
#pragma unroll
            for (int d = 0; d < DD; d++) red[tid * DD + d] += red[(tid + s) * DD + d];
        }
        __syncthreads();
    }
    if (tid < DD) {
        float comp = red[tid] * (1.f / N_ATOMS);
        g_comp[tid] = comp;
        float hv = bat[tid];
#pragma unroll
        for (int c = 0; c < DD; c++)
            hv = fmaf(red[c] * (1.f / N_ATOMS), Wat[tid * DD + c], hv);
        g_hatt[tid] = fmaxf(hv, 0.f);
    }
}

// ---------------- CNN chain kernels ----------------
__global__ void __launch_bounds__(NT) k_gather_w(const int* __restrict__ wd,
                                                 const float* __restrict__ emb) {
    int i = blockIdx.x * NT + threadIdx.x;
    int n = i / DD, d = i - n * DD;
    g_cnn[0][i] = emb[(size_t)wd[n] * DD + d];
}

// one conv layer: 128 rows/block, 2 threads per row (c split 5+5), grid 512
__global__ void __launch_bounds__(NT) k_cnn(int layer, const float* __restrict__ Wc,
                                            const float* __restrict__ bc) {
    __shared__ float sIn[(CROWS + 22) * 11];
    __shared__ ull sW[KS * 50];
    __shared__ ull red[CROWS * 5];
    const int tid = threadIdx.x;
    const int row = tid & (CROWS - 1);
    const int half = tid >> 7;         // 0: c in [0,5), 1: c in [5,10)
    const float* in = g_cnn[layer & 1];
    float*       o  = g_cnn[(layer & 1) ^ 1];
    const float* W  = Wc + layer * KS * KS;
    const float bias = bc[layer];

    for (int i = tid; i < KS * 50; i += NT) {
        int dl = i / 50, rem = i % 50, c = rem / 5, p = rem % 5;
        sW[i] = pack2(W[dl * KS + 11 + c - 2 * p], W[dl * KS + 11 + c - 2 * p - 1]);
    }
    int base = blockIdx.x * CROWS - 11;
    for (int i = tid; i < (CROWS + 22) * DD; i += NT) {
        int rr = i / DD, c = i - rr * DD;
        int g = base + rr;
        sIn[rr * 11 + c] = (g >= 0 && g < L_WORDS) ? in[g * DD + c] : 0.f;
    }
    __syncthreads();

    ull acc[5];
    ull b2 = pack2(bias, bias);
#pragma unroll
    for (int p = 0; p < 5; p++) acc[p] = (half == 0) ? b2 : 0ull;
    const int c0 = half * 5;
#pragma unroll 1
    for (int dl = 0; dl < KS; dl++) {
#pragma unroll
        for (int cc = 0; cc < 5; cc++) {
            int c = c0 + cc;
            float xv = sIn[(row + dl) * 11 + c];
            ull x2 = pack2(xv, xv);
#pragma unroll
            for (int p = 0; p < 5; p++) fma2(acc[p], x2, sW[dl * 50 + c * 5 + p]);
        }
    }

    if (half == 1) {
#pragma unroll
        for (int p = 0; p < 5; p++) red[row * 5 + p] = acc[p];
    }
    __syncthreads();
    if (half == 0) {
        int grow = blockIdx.x * CROWS + row;
#pragma unroll
        for (int p = 0; p < 5; p++) {
            ull s = add2(acc[p], red[row * 5 + p]);
            float v0, v1;
            unpack2(s, v0, v1);
            o[grow * DD + 2 * p]     = fmaxf(v0, 0.f);
            o[grow * DD + 2 * p + 1] = fmaxf(v1, 0.f);
        }
    }
}

// ---------------- join kernels ----------------
__global__ void __launch_bounds__(NT) k_att(const float* __restrict__ Wat,
                                            const float* __restrict__ bat) {
    __shared__ float sWat[DD * DD], sbv[DD], shv[DD];
    __shared__ float red[NT * DD];
    const int tid = threadIdx.x;
    if (tid < DD * DD) sWat[tid] = Wat[tid];
    if (tid < DD) { sbv[tid] = bat[tid]; shv[tid] = g_hatt[tid]; }
    __syncthreads();

    int l = blockIdx.x * NT + tid;
    const float* in = g_cnn[1];
    float x[DD];
#pragma unroll
    for (int c = 0; c < DD; c++) x[c] = in[l * DD + c];
    float hp[DD], wl = 0.f;
#pragma unroll
    for (int u = 0; u < DD; u++) {
        float v = sbv[u];
#pragma unroll
        for (int c = 0; c < DD; c++) v = fmaf(x[c], sWat[u * DD + c], v);
        v = fmaxf(v, 0.f);
        hp[u] = v;
        wl = fmaf(shv[u], v, wl);
    }
    wl = tanhf(wl);
#pragma unroll
    for (int d = 0; d < DD; d++) red[tid * DD + d] = wl * hp[d];
    __syncthreads();
    for (int s = 128; s > 0; s >>= 1) {
        if (tid < s) {
#pragma unroll
            for (int d = 0; d < DD; d++) red[tid * DD + d] += red[(tid + s) * DD + d];
        }
        __syncthreads();
    }
    if (tid < DD) g_part[blockIdx.x * DD + tid] = red[tid];
}

__global__ void __launch_bounds__(NT) k_final(const float* __restrict__ Wout,
                                              const float* __restrict__ bout,
                                              const float* __restrict__ Wint,
                                              const float* __restrict__ bint,
                                              float* __restrict__ out) {
    __shared__ float red[NT * DD];
    __shared__ float cat[20];
    const int tid = threadIdx.x;
#pragma unroll
    for (int d = 0; d < DD; d++) red[tid * DD + d] = g_part[tid * DD + d];
    __syncthreads();
    for (int s = 128; s > 0; s >>= 1) {
        if (tid < s) {
#pragma unroll
            for (int d = 0; d < DD; d++) red[tid * DD + d] += red[(tid + s) * DD + d];
        }
        __syncthreads();
    }
    if (tid < DD) cat[tid] = g_comp[tid];
    if (tid >= DD && tid < 20) cat[tid] = red[tid - DD] * (1.f / L_WORDS);
    __syncthreads();
    if (tid < 32) {
        for (int j = 0; j < 3; j++) {
            float v = 0.f;
            if (tid < 20) {
                v = bout[j * 20 + tid];
                for (int c = 0; c < 20; c++)
                    v = fmaf(cat[c], Wout[j * 400 + tid * 20 + c], v);
                v = fmaxf(v, 0.f);
            }
            __syncwarp();
            if (tid < 20) cat[tid] = v;
            __syncwarp();
        }
        if (tid < 2) {
            float v = bint[tid];
            for (int c = 0; c < 20; c++) v = fmaf(cat[c], Wint[tid * 20 + c], v);
            out[tid] = v;
        }
    }
}

// ---------------- launch: graph with two parallel branches ----------------
extern "C" void kernel_launch(void* const* d_in, const int* in_sizes, int n_in,
                              void* d_out, int out_size) {
    const int*   fp    = (const int*)d_in[0];
    const float* A     = (const float*)d_in[1];
    const int*   words = (const int*)d_in[2];
    const float* embf  = (const float*)d_in[3];
    const float* embw  = (const float*)d_in[4];
    const float* Wg    = (const float*)d_in[5];
    const float* bg    = (const float*)d_in[6];
    const float* Wc    = (const float*)d_in[7];
    const float* bc    = (const float*)d_in[8];
    const float* Wat   = (const float*)d_in[9];
    const float* bat   = (const float*)d_in[10];
    const float* Wout  = (const float*)d_in[11];
    const float* bout  = (const float*)d_in[12];
    const float* Wint  = (const float*)d_in[13];
    const float* bint  = (const float*)d_in[14];
    float* out = (float*)d_out;

    cudaFuncSetAttribute(k_mv0, cudaFuncAttributeMaxDynamicSharedMemorySize, SMEM_BYTES);
    cudaFuncSetAttribute(k_mv,  cudaFuncAttributeMaxDynamicSharedMemorySize, SMEM_BYTES);

    // fork a second stream for the CNN chain (capture-time only cost).
    cudaStream_t sC;
    cudaStreamCreateWithFlags(&sC, cudaStreamNonBlocking);
    cudaEvent_t eFork, eJoin;
    cudaEventCreateWithFlags(&eFork, cudaEventDisableTiming);
    cudaEventCreateWithFlags(&eJoin, cudaEventDisableTiming);

    cudaEventRecord(eFork, 0);
    cudaStreamWaitEvent(sC, eFork, 0);

    // ----- CNN branch (stream sC) -----
    k_gather_w<<<L_WORDS * DD / NT, NT, 0, sC>>>(words, embw);
    k_cnn<<<L_WORDS / CROWS, NT, 0, sC>>>(0, Wc, bc);
    k_cnn<<<L_WORDS / CROWS, NT, 0, sC>>>(1, Wc, bc);
    k_cnn<<<L_WORDS / CROWS, NT, 0, sC>>>(2, Wc, bc);
    cudaEventRecord(eJoin, sC);

    // ----- GNN branch (capture stream) -----
    k_pre<<<N_ATOMS / NT, NT>>>(fp, embf, Wg, bg);
    k_mv0<<<256, NT, SMEM_BYTES>>>(A);
    k_hs<<<N_ATOMS / NT, NT>>>(Wg + DD * DD, bg + DD);
    k_mv<<<256, NT, SMEM_BYTES>>>();
    k_hs<<<N_ATOMS / NT, NT>>>(Wg + 2 * DD * DD, bg + 2 * DD);
    k_mv<<<256, NT, SMEM_BYTES>>>();
    k_comp<<<1, 512>>>(Wat, bat);

    // ----- join + tail -----
    cudaStreamWaitEvent(0, eJoin, 0);
    k_att<<<L_WORDS / NT, NT>>>(Wat, bat);
    k_final<<<1, NT>>>(Wout, bout, Wint, bint, out);
}